// round 10
// baseline (speedup 1.0000x reference)
#include <cuda_runtime.h>
#include <cstdint>

// Problem constants (fixed by reference setup_inputs)
#define BATCH 16
#define NPTS 131072
#define NCH 6
#define KSEL 1024

#define CTAS_PER_B 8              // == cluster size
#define NPC (NPTS / CTAS_PER_B)   // 16384 points per CTA
#define THREADS 512
#define PPT (NPC / THREADS)       // 32 points per thread
#define NGROUPS (PPT / 4)         // 8 float4-groups per thread
#define NWARPS (THREADS / 32)     // 16

__device__ __forceinline__ uint32_t smem_u32(const void* p) {
    uint32_t a;
    asm("{ .reg .u64 t; cvta.to.shared.u64 t, %1; cvt.u32.u64 %0, t; }"
        : "=r"(a) : "l"(p));
    return a;
}
__device__ __forceinline__ uint32_t mapa_rank(uint32_t local_addr, int rank) {
    uint32_t rem;
    asm("mapa.shared::cluster.u32 %0, %1, %2;" : "=r"(rem) : "r"(local_addr), "r"(rank));
    return rem;
}
__device__ __forceinline__ void st_clu_relaxed(uint32_t addr, unsigned long long v) {
    asm volatile("st.relaxed.cluster.shared::cluster.u64 [%0], %1;"
                 :: "r"(addr), "l"(v) : "memory");
}
__device__ __forceinline__ void st_clu_release(uint32_t addr, unsigned long long v) {
    asm volatile("st.release.cluster.shared::cluster.u64 [%0], %1;"
                 :: "r"(addr), "l"(v) : "memory");
}
__device__ __forceinline__ unsigned long long ld_shared_acq(uint32_t addr) {
    unsigned long long v;
    asm volatile("ld.acquire.cluster.shared::cta.u64 %0, [%1];"
                 : "=l"(v) : "r"(addr) : "memory");
    return v;
}

// ---- packed f32x2 helpers (per-lane IEEE rn, bit-identical to scalar) ----
__device__ __forceinline__ unsigned long long add2(unsigned long long a, unsigned long long b) {
    unsigned long long r;
    asm("add.rn.f32x2 %0, %1, %2;" : "=l"(r) : "l"(a), "l"(b));
    return r;
}
__device__ __forceinline__ unsigned long long mul2(unsigned long long a, unsigned long long b) {
    unsigned long long r;
    asm("mul.rn.f32x2 %0, %1, %2;" : "=l"(r) : "l"(a), "l"(b));
    return r;
}
__device__ __forceinline__ unsigned long long fma2(unsigned long long a, unsigned long long b,
                                                   unsigned long long c) {
    unsigned long long r;
    asm("fma.rn.f32x2 %0, %1, %2, %3;" : "=l"(r) : "l"(a), "l"(b), "l"(c));
    return r;
}
__device__ __forceinline__ void unpack2(float& lo, float& hi, unsigned long long v) {
    asm("mov.b64 {%0, %1}, %2;" : "=f"(lo), "=f"(hi) : "l"(v));
}
__device__ __forceinline__ unsigned long long pack2(float lo, float hi) {
    unsigned long long r;
    asm("mov.b64 %0, {%1, %2};" : "=l"(r) : "f"(lo), "f"(hi));
    return r;
}
__device__ __forceinline__ unsigned long long bcast2(float v) {
    unsigned long long r;
    asm("mov.b64 %0, {%1, %1};" : "=l"(r) : "f"(v));
    return r;
}

// Distance formula (FROZEN, bit-exact vs reference):
//   d = fma(dz,dz, fma(dx,dx, dy*dy)),  dx = x + (-qx) etc.

__global__ __launch_bounds__(THREADS, 1) __cluster_dims__(CTAS_PER_B, 1, 1)
void fps_kernel(const float* __restrict__ pts, float* __restrict__ out) {
    extern __shared__ float sh[];
    float* sx = sh;
    float* sy = sh + NPC;
    float* sz = sh + 2 * NPC;
    __shared__ unsigned long long sred[2][NWARPS];            // CTA reduce, parity-buffered
    __shared__ unsigned long long scand[2][CTAS_PER_B][4];    // peer candidates {pk, xy, z, pad}
    __shared__ unsigned long long sflag[2][CTAS_PER_B];       // iteration-tag flags
    __shared__ unsigned int widx_hist[KSEL];                  // winner history (rank-0 gather)

    const int tid = threadIdx.x;
    const int b   = blockIdx.x / CTAS_PER_B;
    const int c   = blockIdx.x % CTAS_PER_B;                  // == cluster rank
    const float* base = pts + (size_t)b * NPTS * NCH;
    const int p0 = c * NPC;

    // Stage this CTA's xyz slice into SMEM.
    for (int i = tid; i < NPC; i += THREADS) {
        const float* r = base + (size_t)(p0 + i) * NCH;
        sx[i] = r[0];
        sy[i] = r[1];
        sz[i] = r[2];
    }
    // Init flags (0 never equals any it in [1,1023]).
    if (tid < 2 * CTAS_PER_B) (&sflag[0][0])[tid] = 0ULL;

    float dist[PPT];
#pragma unroll
    for (int j = 0; j < PPT; ++j) dist[j] = __int_as_float(0x7f800000); // +inf

    float qx = base[0], qy = base[1], qz = base[2];
    if (c == 0 && tid < NCH) {
        out[(size_t)b * KSEL * NCH + tid] = base[tid];        // row 0 = start point
    }
    __syncthreads();
    // One-time: all flags initialized in every CTA before any peer publishes.
    asm volatile("barrier.cluster.arrive.aligned;" ::: "memory");
    asm volatile("barrier.cluster.wait.aligned;"   ::: "memory");

    const int lane = tid & 31;
    const int warp = tid >> 5;

    const ulonglong2* sx2 = (const ulonglong2*)sx;
    const ulonglong2* sy2 = (const ulonglong2*)sy;
    const ulonglong2* sz2 = (const ulonglong2*)sz;

    for (int it = 1; it < KSEL; ++it) {
        const unsigned long long nqx2 = bcast2(-qx);
        const unsigned long long nqy2 = bcast2(-qy);
        const unsigned long long nqz2 = bcast2(-qz);

        float best = -1.0f;
        unsigned bidx = 0;

#pragma unroll
        for (int g = 0; g < NGROUPS; ++g) {
            const int e = g * THREADS + tid;                  // conflict-free LDS.128
            ulonglong2 X = sx2[e];
            ulonglong2 Y = sy2[e];
            ulonglong2 Z = sz2[e];
            const unsigned gi = (unsigned)(p0 + (e << 2));
            const int j = g * 4;
            {
                unsigned long long dx = add2(X.x, nqx2);
                unsigned long long dy = add2(Y.x, nqy2);
                unsigned long long dz = add2(Z.x, nqz2);
                unsigned long long d2 = fma2(dz, dz, fma2(dx, dx, mul2(dy, dy)));
                float d0, d1; unpack2(d0, d1, d2);
                float n0 = fminf(dist[j + 0], d0); dist[j + 0] = n0;
                if (n0 > best) { best = n0; bidx = gi + 0; }
                float n1 = fminf(dist[j + 1], d1); dist[j + 1] = n1;
                if (n1 > best) { best = n1; bidx = gi + 1; }
            }
            {
                unsigned long long dx = add2(X.y, nqx2);
                unsigned long long dy = add2(Y.y, nqy2);
                unsigned long long dz = add2(Z.y, nqz2);
                unsigned long long d2 = fma2(dz, dz, fma2(dx, dx, mul2(dy, dy)));
                float d0, d1; unpack2(d0, d1, d2);
                float n0 = fminf(dist[j + 2], d0); dist[j + 2] = n0;
                if (n0 > best) { best = n0; bidx = gi + 2; }
                float n1 = fminf(dist[j + 3], d1); dist[j + 3] = n1;
                if (n1 > best) { best = n1; bidx = gi + 3; }
            }
        }

        // Pack (dist_bits << 32) | ~idx : max picks max dist, smallest idx on tie.
        unsigned long long pk =
            ((unsigned long long)__float_as_uint(best) << 32) |
            (unsigned long long)(~bidx);

        // --- warp argmax reduce ---
#pragma unroll
        for (int off = 16; off > 0; off >>= 1) {
            unsigned long long o = __shfl_down_sync(0xffffffffu, pk, off);
            if (o > pk) pk = o;
        }
        const int par = it & 1;
        if (lane == 0) sred[par][warp] = pk;
        __syncthreads();                                      // the ONLY barrier per iter

        // --- warp0: CTA reduce; lanes 0-7 push candidate into every rank's SMEM ---
        if (warp == 0) {
            unsigned long long v = (lane < NWARPS) ? sred[par][lane] : 0ULL;
#pragma unroll
            for (int off = 8; off > 0; off >>= 1) {
                unsigned long long o = __shfl_xor_sync(0xffffffffu, v, off);
                if (o > v) v = o;
            }
            if (lane < CTAS_PER_B) {
                unsigned widxL = ~(unsigned)(v & 0xffffffffULL);
                int local = (int)widxL - p0;                  // winner is in OUR slice
                float wx = sx[local], wy = sy[local], wz = sz[local];  // bcast LDS
                uint32_t ca = mapa_rank(smem_u32(&scand[par][c][0]), lane);
                uint32_t fa = mapa_rank(smem_u32(&sflag[par][c]),    lane);
                st_clu_relaxed(ca,      v);
                st_clu_relaxed(ca + 8,  pack2(wx, wy));
                st_clu_relaxed(ca + 16, pack2(wz, 0.0f));
                st_clu_release(fa, (unsigned long long)it);   // flag = iteration tag
            }
        }

        // --- every warp: poll LOCAL flags, then select global winner locally ---
        unsigned long long pkj = 0, xyj = 0, zj = 0;
        if (lane < CTAS_PER_B) {
            uint32_t fa = smem_u32(&sflag[par][lane]);
            while (ld_shared_acq(fa) != (unsigned long long)it) { }
            pkj = scand[par][lane][0];
            xyj = scand[par][lane][1];
            zj  = scand[par][lane][2];
        }
        unsigned long long m = pkj;
#pragma unroll
        for (int off = 4; off > 0; off >>= 1) {
            unsigned long long o = __shfl_xor_sync(0xffffffffu, m, off);
            if (o > m) m = o;
        }
        unsigned long long m0 = __shfl_sync(0xffffffffu, m, 0);
        unsigned bal = __ballot_sync(0xffffffffu, pkj == m0);
        int win = __ffs(bal) - 1;                             // smallest CTA on tie
        unsigned long long xyw = __shfl_sync(0xffffffffu, xyj, win);
        unsigned long long zw  = __shfl_sync(0xffffffffu, zj,  win);
        float dummy;
        unpack2(qx, qy, xyw);
        unpack2(qz, dummy, zw);

        if (c == 0 && warp == 0 && lane == 0) {
            widx_hist[it] = ~(unsigned)(m0 & 0xffffffffULL);
        }
    }

    // --- final output gather (off the per-iteration critical path) ---
    __syncthreads();
    if (c == 0) {
        for (int i = tid; i < (KSEL - 1) * NCH; i += THREADS) {
            int itr = i / NCH + 1;
            int ch  = i % NCH;
            out[((size_t)b * KSEL + itr) * NCH + ch] =
                base[(size_t)widx_hist[itr] * NCH + ch];
        }
    }
    // Keep peer SMEM alive until all remote traffic has landed.
    asm volatile("barrier.cluster.arrive.aligned;" ::: "memory");
    asm volatile("barrier.cluster.wait.aligned;"   ::: "memory");
}

extern "C" void kernel_launch(void* const* d_in, const int* in_sizes, int n_in,
                              void* d_out, int out_size) {
    const float* pts = (const float*)d_in[0];
    float* out = (float*)d_out;

    static bool attr_set = false;
    if (!attr_set) {
        cudaFuncSetAttribute(fps_kernel,
                             cudaFuncAttributeMaxDynamicSharedMemorySize,
                             3 * NPC * sizeof(float));
        attr_set = true;
    }

    fps_kernel<<<BATCH * CTAS_PER_B, THREADS, 3 * NPC * sizeof(float)>>>(pts, out);
}

// round 11
// speedup vs baseline: 1.0028x; 1.0028x over previous
#include <cuda_runtime.h>
#include <cstdint>

// Problem constants (fixed by reference setup_inputs)
#define BATCH 16
#define NPTS 131072
#define NCH 6
#define KSEL 1024

#define CTAS_PER_B 8              // == cluster size
#define NPC (NPTS / CTAS_PER_B)   // 16384 points per CTA
#define THREADS 512
#define PPT (NPC / THREADS)       // 32 points per thread
#define NGROUPS (PPT / 4)         // 8 float4-groups per thread
#define NWARPS (THREADS / 32)     // 16

__device__ __forceinline__ uint32_t smem_u32(const void* p) {
    uint32_t a;
    asm("{ .reg .u64 t; cvta.to.shared.u64 t, %1; cvt.u32.u64 %0, t; }"
        : "=r"(a) : "l"(p));
    return a;
}
__device__ __forceinline__ uint32_t mapa_rank(uint32_t local_addr, int rank) {
    uint32_t rem;
    asm("mapa.shared::cluster.u32 %0, %1, %2;" : "=r"(rem) : "r"(local_addr), "r"(rank));
    return rem;
}
__device__ __forceinline__ void st_clu_relaxed(uint32_t addr, unsigned long long v) {
    asm volatile("st.relaxed.cluster.shared::cluster.u64 [%0], %1;"
                 :: "r"(addr), "l"(v) : "memory");
}
__device__ __forceinline__ void st_clu_release(uint32_t addr, unsigned long long v) {
    asm volatile("st.release.cluster.shared::cluster.u64 [%0], %1;"
                 :: "r"(addr), "l"(v) : "memory");
}
__device__ __forceinline__ unsigned long long ld_vol_shared(uint32_t addr) {
    unsigned long long v;
    asm volatile("ld.volatile.shared.u64 %0, [%1];" : "=l"(v) : "r"(addr) : "memory");
    return v;
}
__device__ __forceinline__ unsigned long long ld_acq_cluster_shared(uint32_t addr) {
    unsigned long long v;
    asm volatile("ld.acquire.cluster.shared::cta.u64 %0, [%1];"
                 : "=l"(v) : "r"(addr) : "memory");
    return v;
}

// ---- packed f32x2 helpers (per-lane IEEE rn, bit-identical to scalar) ----
__device__ __forceinline__ unsigned long long add2(unsigned long long a, unsigned long long b) {
    unsigned long long r;
    asm("add.rn.f32x2 %0, %1, %2;" : "=l"(r) : "l"(a), "l"(b));
    return r;
}
__device__ __forceinline__ unsigned long long mul2(unsigned long long a, unsigned long long b) {
    unsigned long long r;
    asm("mul.rn.f32x2 %0, %1, %2;" : "=l"(r) : "l"(a), "l"(b));
    return r;
}
__device__ __forceinline__ unsigned long long fma2(unsigned long long a, unsigned long long b,
                                                   unsigned long long c) {
    unsigned long long r;
    asm("fma.rn.f32x2 %0, %1, %2, %3;" : "=l"(r) : "l"(a), "l"(b), "l"(c));
    return r;
}
__device__ __forceinline__ void unpack2(float& lo, float& hi, unsigned long long v) {
    asm("mov.b64 {%0, %1}, %2;" : "=f"(lo), "=f"(hi) : "l"(v));
}
__device__ __forceinline__ unsigned long long pack2(float lo, float hi) {
    unsigned long long r;
    asm("mov.b64 %0, {%1, %2};" : "=l"(r) : "f"(lo), "f"(hi));
    return r;
}
__device__ __forceinline__ unsigned long long bcast2(float v) {
    unsigned long long r;
    asm("mov.b64 %0, {%1, %1};" : "=l"(r) : "f"(v));
    return r;
}

// Distance formula (FROZEN, bit-exact vs reference):
//   d = fma(dz,dz, fma(dx,dx, dy*dy)),  dx = x + (-qx) etc.

__global__ __launch_bounds__(THREADS, 1) __cluster_dims__(CTAS_PER_B, 1, 1)
void fps_kernel(const float* __restrict__ pts, float* __restrict__ out) {
    extern __shared__ float sh[];
    float* sx = sh;
    float* sy = sh + NPC;
    float* sz = sh + 2 * NPC;
    __shared__ unsigned long long sred[2][NWARPS];            // CTA reduce, parity-buffered
    __shared__ unsigned long long scand[2][CTAS_PER_B][4];    // peer candidates {pk, xy, z, pad}
    __shared__ unsigned long long sflag[2][CTAS_PER_B];       // iteration-tag flags
    __shared__ unsigned long long sbc[2];                     // winner broadcast {xy, z}
    __shared__ unsigned int widx_hist[KSEL];                  // winner history (rank-0 gather)

    const int tid = threadIdx.x;
    const int b   = blockIdx.x / CTAS_PER_B;
    const int c   = blockIdx.x % CTAS_PER_B;                  // == cluster rank
    const float* base = pts + (size_t)b * NPTS * NCH;
    const int p0 = c * NPC;

    // Stage this CTA's xyz slice into SMEM.
    for (int i = tid; i < NPC; i += THREADS) {
        const float* r = base + (size_t)(p0 + i) * NCH;
        sx[i] = r[0];
        sy[i] = r[1];
        sz[i] = r[2];
    }
    // Init flags (0 never equals any it in [1,1023]).
    if (tid < 2 * CTAS_PER_B) (&sflag[0][0])[tid] = 0ULL;

    float dist[PPT];
#pragma unroll
    for (int j = 0; j < PPT; ++j) dist[j] = __int_as_float(0x7f800000); // +inf

    float qx = base[0], qy = base[1], qz = base[2];
    if (c == 0 && tid < NCH) {
        out[(size_t)b * KSEL * NCH + tid] = base[tid];        // row 0 = start point
    }
    __syncthreads();
    // One-time: all flags initialized in every CTA before any peer publishes.
    asm volatile("barrier.cluster.arrive.aligned;" ::: "memory");
    asm volatile("barrier.cluster.wait.aligned;"   ::: "memory");

    const int lane = tid & 31;
    const int warp = tid >> 5;

    const ulonglong2* sx2 = (const ulonglong2*)sx;
    const ulonglong2* sy2 = (const ulonglong2*)sy;
    const ulonglong2* sz2 = (const ulonglong2*)sz;

    for (int it = 1; it < KSEL; ++it) {
        const unsigned long long nqx2 = bcast2(-qx);
        const unsigned long long nqy2 = bcast2(-qy);
        const unsigned long long nqz2 = bcast2(-qz);

        float best = -1.0f;
        unsigned bidx = 0;

#pragma unroll
        for (int g = 0; g < NGROUPS; ++g) {
            const int e = g * THREADS + tid;                  // conflict-free LDS.128
            ulonglong2 X = sx2[e];
            ulonglong2 Y = sy2[e];
            ulonglong2 Z = sz2[e];
            const unsigned gi = (unsigned)(p0 + (e << 2));
            const int j = g * 4;
            {
                unsigned long long dx = add2(X.x, nqx2);
                unsigned long long dy = add2(Y.x, nqy2);
                unsigned long long dz = add2(Z.x, nqz2);
                unsigned long long d2 = fma2(dz, dz, fma2(dx, dx, mul2(dy, dy)));
                float d0, d1; unpack2(d0, d1, d2);
                float n0 = fminf(dist[j + 0], d0); dist[j + 0] = n0;
                if (n0 > best) { best = n0; bidx = gi + 0; }
                float n1 = fminf(dist[j + 1], d1); dist[j + 1] = n1;
                if (n1 > best) { best = n1; bidx = gi + 1; }
            }
            {
                unsigned long long dx = add2(X.y, nqx2);
                unsigned long long dy = add2(Y.y, nqy2);
                unsigned long long dz = add2(Z.y, nqz2);
                unsigned long long d2 = fma2(dz, dz, fma2(dx, dx, mul2(dy, dy)));
                float d0, d1; unpack2(d0, d1, d2);
                float n0 = fminf(dist[j + 2], d0); dist[j + 2] = n0;
                if (n0 > best) { best = n0; bidx = gi + 2; }
                float n1 = fminf(dist[j + 3], d1); dist[j + 3] = n1;
                if (n1 > best) { best = n1; bidx = gi + 3; }
            }
        }

        // Pack (dist_bits << 32) | ~idx : max picks max dist, smallest idx on tie.
        unsigned long long pk =
            ((unsigned long long)__float_as_uint(best) << 32) |
            (unsigned long long)(~bidx);

        // --- warp argmax reduce ---
#pragma unroll
        for (int off = 16; off > 0; off >>= 1) {
            unsigned long long o = __shfl_down_sync(0xffffffffu, pk, off);
            if (o > pk) pk = o;
        }
        const int par = it & 1;
        if (lane == 0) sred[par][warp] = pk;
        __syncthreads();                                      // bar1: sred complete

        // --- warp0 only: CTA reduce; push candidate into every rank's SMEM;
        //     poll LOCAL flags (cheap volatile LDS); select; broadcast via sbc ---
        if (warp == 0) {
            unsigned long long v = (lane < NWARPS) ? sred[par][lane] : 0ULL;
#pragma unroll
            for (int off = 8; off > 0; off >>= 1) {
                unsigned long long o = __shfl_xor_sync(0xffffffffu, v, off);
                if (o > v) v = o;
            }
            if (lane < CTAS_PER_B) {
                unsigned widxL = ~(unsigned)(v & 0xffffffffULL);
                int local = (int)widxL - p0;                  // winner is in OUR slice
                float wx = sx[local], wy = sy[local], wz = sz[local];  // bcast LDS
                uint32_t ca = mapa_rank(smem_u32(&scand[par][c][0]), lane);
                uint32_t fa = mapa_rank(smem_u32(&sflag[par][c]),    lane);
                st_clu_relaxed(ca,      v);
                st_clu_relaxed(ca + 8,  pack2(wx, wy));
                st_clu_relaxed(ca + 16, pack2(wz, 0.0f));
                st_clu_release(fa, (unsigned long long)it);   // flag = iteration tag
            }
            // Poll local flags with plain volatile LDS (29-cyc rounds), then one
            // acquire load to synchronize-with the peer's release store.
            unsigned long long pkj = 0, xyj = 0, zj = 0;
            if (lane < CTAS_PER_B) {
                uint32_t fa = smem_u32(&sflag[par][lane]);
                while (ld_vol_shared(fa) != (unsigned long long)it) { }
                (void)ld_acq_cluster_shared(fa);              // acquire: scand now visible
                pkj = scand[par][lane][0];
                xyj = scand[par][lane][1];
                zj  = scand[par][lane][2];
            }
            unsigned long long m = pkj;
#pragma unroll
            for (int off = 4; off > 0; off >>= 1) {
                unsigned long long o = __shfl_xor_sync(0xffffffffu, m, off);
                if (o > m) m = o;
            }
            unsigned long long m0 = __shfl_sync(0xffffffffu, m, 0);
            unsigned bal = __ballot_sync(0xffffffffu, pkj == m0);
            int win = __ffs(bal) - 1;                         // smallest CTA on tie
            if (lane == win) {
                sbc[0] = xyj;
                sbc[1] = zj;
            }
            if (c == 0 && lane == 0) {
                widx_hist[it] = ~(unsigned)(m0 & 0xffffffffULL);
            }
        }
        __syncthreads();                                      // bar2: winner visible

        float dummy;
        unpack2(qx, qy, sbc[0]);
        unpack2(qz, dummy, sbc[1]);
    }

    // --- final output gather (off the per-iteration critical path) ---
    if (c == 0) {
        for (int i = tid; i < (KSEL - 1) * NCH; i += THREADS) {
            int itr = i / NCH + 1;
            int ch  = i % NCH;
            out[((size_t)b * KSEL + itr) * NCH + ch] =
                base[(size_t)widx_hist[itr] * NCH + ch];
        }
    }
    // Keep peer SMEM alive until all remote traffic has landed.
    asm volatile("barrier.cluster.arrive.aligned;" ::: "memory");
    asm volatile("barrier.cluster.wait.aligned;"   ::: "memory");
}

extern "C" void kernel_launch(void* const* d_in, const int* in_sizes, int n_in,
                              void* d_out, int out_size) {
    const float* pts = (const float*)d_in[0];
    float* out = (float*)d_out;

    static bool attr_set = false;
    if (!attr_set) {
        cudaFuncSetAttribute(fps_kernel,
                             cudaFuncAttributeMaxDynamicSharedMemorySize,
                             3 * NPC * sizeof(float));
        attr_set = true;
    }

    fps_kernel<<<BATCH * CTAS_PER_B, THREADS, 3 * NPC * sizeof(float)>>>(pts, out);
}

// round 12
// speedup vs baseline: 2.9823x; 2.9740x over previous
#include <cuda_runtime.h>
#include <cstdint>

// Problem constants (fixed by reference setup_inputs)
#define BATCH 16
#define NPTS 131072
#define NCH 6
#define KSEL 1024

#define CTAS_PER_B 8
#define NPC (NPTS / CTAS_PER_B)   // 16384 points per CTA
#define THREADS 512
#define PPT (NPC / THREADS)       // 32 points per thread
#define NGROUPS (PPT / 4)         // 8 float4-groups per thread
#define NWARPS (THREADS / 32)     // 16

// Per-CTA publish slots, 32B each, PER ITERATION (zeroed by init kernel):
//   [0..1] = b128 A {pk, xy}  : pk = (dist_bits<<32 | ~idx) != 0  -> A valid
//   [2..3] = b128 B {z, tag}  : tag = 1                           -> B valid
// Each b128 is single-copy atomic => halves self-validate; no release/acquire,
// and the poller needs exactly ONE concurrent load round.
__device__ unsigned long long g_pub[BATCH][KSEL][CTAS_PER_B][4];

__global__ void fps_init_kernel() {
    unsigned long long* p = &g_pub[0][0][0][0];
    const int n = BATCH * KSEL * CTAS_PER_B * 4;
    for (int i = blockIdx.x * blockDim.x + threadIdx.x; i < n;
         i += gridDim.x * blockDim.x)
        p[i] = 0ULL;
}

__device__ __forceinline__ void st_b128_relaxed(unsigned long long* p,
                                                unsigned long long lo,
                                                unsigned long long hi) {
    asm volatile(
        "{ .reg .b128 t; mov.b128 t, {%1, %2}; st.relaxed.gpu.global.b128 [%0], t; }"
        :: "l"(p), "l"(lo), "l"(hi) : "memory");
}
__device__ __forceinline__ void ld_b128_relaxed(unsigned long long& lo,
                                                unsigned long long& hi,
                                                const unsigned long long* p) {
    asm volatile(
        "{ .reg .b128 t; ld.relaxed.gpu.global.b128 t, [%2]; mov.b128 {%0, %1}, t; }"
        : "=l"(lo), "=l"(hi) : "l"(p) : "memory");
}

// ---- packed f32x2 helpers (per-lane IEEE rn, bit-identical to scalar) ----
__device__ __forceinline__ unsigned long long add2(unsigned long long a, unsigned long long b) {
    unsigned long long r;
    asm("add.rn.f32x2 %0, %1, %2;" : "=l"(r) : "l"(a), "l"(b));
    return r;
}
__device__ __forceinline__ unsigned long long mul2(unsigned long long a, unsigned long long b) {
    unsigned long long r;
    asm("mul.rn.f32x2 %0, %1, %2;" : "=l"(r) : "l"(a), "l"(b));
    return r;
}
__device__ __forceinline__ unsigned long long fma2(unsigned long long a, unsigned long long b,
                                                   unsigned long long c) {
    unsigned long long r;
    asm("fma.rn.f32x2 %0, %1, %2, %3;" : "=l"(r) : "l"(a), "l"(b), "l"(c));
    return r;
}
__device__ __forceinline__ void unpack2(float& lo, float& hi, unsigned long long v) {
    asm("mov.b64 {%0, %1}, %2;" : "=f"(lo), "=f"(hi) : "l"(v));
}
__device__ __forceinline__ unsigned long long pack2(float lo, float hi) {
    unsigned long long r;
    asm("mov.b64 %0, {%1, %2};" : "=l"(r) : "f"(lo), "f"(hi));
    return r;
}
__device__ __forceinline__ unsigned long long bcast2(float v) {
    unsigned long long r;
    asm("mov.b64 %0, {%1, %1};" : "=l"(r) : "f"(v));
    return r;
}

// Distance formula (FROZEN, bit-exact vs reference):
//   d = fma(dz,dz, fma(dx,dx, dy*dy)),  dx = x + (-qx) etc.

__global__ __launch_bounds__(THREADS, 1)
void fps_kernel(const float* __restrict__ pts, float* __restrict__ out) {
    extern __shared__ float sh[];
    float* sx = sh;
    float* sy = sh + NPC;
    float* sz = sh + 2 * NPC;
    __shared__ unsigned long long sred[2][NWARPS];   // CTA reduce, parity-buffered
    __shared__ unsigned long long sbc[2];            // winner broadcast {xy, z}
    __shared__ unsigned int widx_hist[KSEL];         // winner history (rank-0 gather)

    const int tid = threadIdx.x;
    const int b   = blockIdx.x / CTAS_PER_B;
    const int c   = blockIdx.x % CTAS_PER_B;
    const float* base = pts + (size_t)b * NPTS * NCH;
    const int p0 = c * NPC;

    // Stage this CTA's xyz slice into SMEM.
    for (int i = tid; i < NPC; i += THREADS) {
        const float* r = base + (size_t)(p0 + i) * NCH;
        sx[i] = r[0];
        sy[i] = r[1];
        sz[i] = r[2];
    }

    float dist[PPT];
#pragma unroll
    for (int j = 0; j < PPT; ++j) dist[j] = __int_as_float(0x7f800000); // +inf

    float qx = base[0], qy = base[1], qz = base[2];
    if (c == 0 && tid < NCH) {
        out[(size_t)b * KSEL * NCH + tid] = base[tid];   // row 0 = start point
    }
    __syncthreads();

    const int lane = tid & 31;
    const int warp = tid >> 5;

    const ulonglong2* sx2 = (const ulonglong2*)sx;
    const ulonglong2* sy2 = (const ulonglong2*)sy;
    const ulonglong2* sz2 = (const ulonglong2*)sz;

    for (int it = 1; it < KSEL; ++it) {
        const unsigned long long nqx2 = bcast2(-qx);
        const unsigned long long nqy2 = bcast2(-qy);
        const unsigned long long nqz2 = bcast2(-qz);

        float best = -1.0f;
        unsigned bidx = 0;

#pragma unroll
        for (int g = 0; g < NGROUPS; ++g) {
            const int e = g * THREADS + tid;             // conflict-free LDS.128
            ulonglong2 X = sx2[e];
            ulonglong2 Y = sy2[e];
            ulonglong2 Z = sz2[e];
            const unsigned gi = (unsigned)(p0 + (e << 2));
            const int j = g * 4;
            {
                unsigned long long dx = add2(X.x, nqx2);
                unsigned long long dy = add2(Y.x, nqy2);
                unsigned long long dz = add2(Z.x, nqz2);
                unsigned long long d2 = fma2(dz, dz, fma2(dx, dx, mul2(dy, dy)));
                float d0, d1; unpack2(d0, d1, d2);
                float n0 = fminf(dist[j + 0], d0); dist[j + 0] = n0;
                if (n0 > best) { best = n0; bidx = gi + 0; }
                float n1 = fminf(dist[j + 1], d1); dist[j + 1] = n1;
                if (n1 > best) { best = n1; bidx = gi + 1; }
            }
            {
                unsigned long long dx = add2(X.y, nqx2);
                unsigned long long dy = add2(Y.y, nqy2);
                unsigned long long dz = add2(Z.y, nqz2);
                unsigned long long d2 = fma2(dz, dz, fma2(dx, dx, mul2(dy, dy)));
                float d0, d1; unpack2(d0, d1, d2);
                float n0 = fminf(dist[j + 2], d0); dist[j + 2] = n0;
                if (n0 > best) { best = n0; bidx = gi + 2; }
                float n1 = fminf(dist[j + 3], d1); dist[j + 3] = n1;
                if (n1 > best) { best = n1; bidx = gi + 3; }
            }
        }

        // Pack (dist_bits << 32) | ~idx : max picks max dist, smallest idx on tie.
        unsigned long long pk =
            ((unsigned long long)__float_as_uint(best) << 32) |
            (unsigned long long)(~bidx);

        // --- warp argmax reduce ---
#pragma unroll
        for (int off = 16; off > 0; off >>= 1) {
            unsigned long long o = __shfl_down_sync(0xffffffffu, pk, off);
            if (o > pk) pk = o;
        }
        const int par = it & 1;
        if (lane == 0) sred[par][warp] = pk;
        __syncthreads();                                 // bar1: sred complete

        // --- warp0 only: CTA reduce, publish, poll peers, select, broadcast ---
        if (warp == 0) {
            unsigned long long v = (lane < NWARPS) ? sred[par][lane] : 0ULL;
#pragma unroll
            for (int off = 8; off > 0; off >>= 1) {
                unsigned long long o = __shfl_xor_sync(0xffffffffu, v, off);
                if (o > v) v = o;
            }
            if (lane == 0) {
                unsigned widxL = ~(unsigned)(v & 0xffffffffULL);
                int local = (int)widxL - p0;             // winner is in OUR slice
                float wx = sx[local], wy = sy[local], wz = sz[local];
                unsigned long long* ent = &g_pub[b][it][c][0];
                st_b128_relaxed(&ent[2], pack2(wz, 0.0f), 1ULL);   // B {z, tag}
                st_b128_relaxed(&ent[0], v, pack2(wx, wy));        // A {pk, xy}
            }
            // Lanes 0-7 poll the 8 per-CTA slots: ONE concurrent round per retry.
            unsigned long long pkj = 0, xyj = 0, zj = 0;
            if (lane < CTAS_PER_B) {
                const unsigned long long* ent = &g_pub[b][it][lane][0];
                unsigned long long a0, a1, b0, b1;
                do {
                    ld_b128_relaxed(a0, a1, &ent[0]);    // both loads in flight
                    ld_b128_relaxed(b0, b1, &ent[2]);    // before the check
                } while (a0 == 0ULL || b1 == 0ULL);
                pkj = a0; xyj = a1; zj = b0;
            }
            unsigned long long m = pkj;
#pragma unroll
            for (int off = 4; off > 0; off >>= 1) {
                unsigned long long o = __shfl_xor_sync(0xffffffffu, m, off);
                if (o > m) m = o;
            }
            unsigned long long m0 = __shfl_sync(0xffffffffu, m, 0);
            unsigned bal = __ballot_sync(0xffffffffu, pkj == m0);
            int win = __ffs(bal) - 1;                    // smallest CTA on tie
            if (lane == win) {
                sbc[0] = xyj;
                sbc[1] = zj;
            }
            if (c == 0 && lane == 0) {
                widx_hist[it] = ~(unsigned)(m0 & 0xffffffffULL);
            }
        }
        __syncthreads();                                 // bar2: winner visible

        float dummy;
        unpack2(qx, qy, sbc[0]);
        unpack2(qz, dummy, sbc[1]);
    }

    // --- final output gather (off the per-iteration critical path) ---
    if (c == 0) {
        for (int i = tid; i < (KSEL - 1) * NCH; i += THREADS) {
            int itr = i / NCH + 1;
            int ch  = i % NCH;
            out[((size_t)b * KSEL + itr) * NCH + ch] =
                base[(size_t)widx_hist[itr] * NCH + ch];
        }
    }
}

extern "C" void kernel_launch(void* const* d_in, const int* in_sizes, int n_in,
                              void* d_out, int out_size) {
    const float* pts = (const float*)d_in[0];
    float* out = (float*)d_out;

    static bool attr_set = false;
    if (!attr_set) {
        cudaFuncSetAttribute(fps_kernel,
                             cudaFuncAttributeMaxDynamicSharedMemorySize,
                             3 * NPC * sizeof(float));
        attr_set = true;
    }

    fps_init_kernel<<<256, 512>>>();
    fps_kernel<<<BATCH * CTAS_PER_B, THREADS, 3 * NPC * sizeof(float)>>>(pts, out);
}